// round 14
// baseline (speedup 1.0000x reference)
#include <cuda_runtime.h>
#include <cuda_fp16.h>
#include <math.h>
#include <stdint.h>

#define B_ 2
#define L_ 64
#define C_ 256
#define S_ 256
#define D_ 512
#define NQ (B_*L_*C_)   /* 32768 rows */

// Scratch (module-load allocated; no runtime allocs) — fp16 pipeline
__device__ __half g_qh[(size_t)NQ * D_];
__device__ __half g_ql[(size_t)NQ * D_];
__device__ __half g_kh[(size_t)NQ * D_];
__device__ __half g_kl[(size_t)NQ * D_];
__device__ __half g_vh[(size_t)NQ * D_];
__device__ __half g_oh[(size_t)NQ * D_];
__device__ __half g_whq [(size_t)D_ * D_];
__device__ __half g_whkv[(size_t)D_ * D_];
__device__ __half g_who [(size_t)D_ * D_];

// ---------------------------------------------------------------------------
// helpers
// ---------------------------------------------------------------------------
__device__ __forceinline__ uint32_t smem_u32(const void* p) {
    uint32_t a;
    asm("{ .reg .u64 t; cvta.to.shared.u64 t, %1; cvt.u32.u64 %0, t; }"
        : "=r"(a) : "l"(p));
    return a;
}
__device__ __forceinline__ uint32_t pack_h2(float a, float b) {
    __half2 h = __floats2half2_rn(a, b);
    return *(uint32_t*)&h;
}
__device__ __forceinline__ void split2h(float a, float b, uint32_t& h, uint32_t& l) {
    __half ha = __float2half_rn(a);
    __half hb = __float2half_rn(b);
    __half la = __float2half_rn(a - __half2float(ha));
    __half lb = __float2half_rn(b - __half2float(hb));
    __half2 hp = __halves2half2(ha, hb);
    __half2 lp = __halves2half2(la, lb);
    h = *(uint32_t*)&hp;
    l = *(uint32_t*)&lp;
}
__device__ __forceinline__ void mma_f16(float d[4], const uint32_t a[4],
                                        const uint32_t b[2]) {
    asm volatile(
        "mma.sync.aligned.m16n8k16.row.col.f32.f16.f16.f32 "
        "{%0,%1,%2,%3}, {%4,%5,%6,%7}, {%8,%9}, {%0,%1,%2,%3};\n"
        : "+f"(d[0]), "+f"(d[1]), "+f"(d[2]), "+f"(d[3])
        : "r"(a[0]), "r"(a[1]), "r"(a[2]), "r"(a[3]),
          "r"(b[0]), "r"(b[1]));
}
__device__ __forceinline__ void ldsm_x4(uint32_t r[4], uint32_t addr) {
    asm volatile("ldmatrix.sync.aligned.m8n8.x4.shared.b16 {%0,%1,%2,%3}, [%4];"
        : "=r"(r[0]), "=r"(r[1]), "=r"(r[2]), "=r"(r[3]) : "r"(addr));
}
__device__ __forceinline__ void ldsm_x4_t(uint32_t r[4], uint32_t addr) {
    asm volatile("ldmatrix.sync.aligned.m8n8.x4.trans.shared.b16 {%0,%1,%2,%3}, [%4];"
        : "=r"(r[0]), "=r"(r[1]), "=r"(r[2]), "=r"(r[3]) : "r"(addr));
}
__device__ __forceinline__ void cp16(uint32_t smem_dst, const void* gptr) {
    asm volatile("cp.async.ca.shared.global [%0], [%1], 16;"
                 :: "r"(smem_dst), "l"(gptr));
}
#define CP_COMMIT() asm volatile("cp.async.commit_group;" ::: "memory")
#define CP_WAIT0()  asm volatile("cp.async.wait_group 0;" ::: "memory")

// ---------------------------------------------------------------------------
// Weight convert: 3x fp32 [512x512] -> fp16 in one launch
// ---------------------------------------------------------------------------
__global__ __launch_bounds__(256) void convert_w3(
    const float* __restrict__ W0, __half* __restrict__ H0,
    const float* __restrict__ W1, __half* __restrict__ H1,
    const float* __restrict__ W2, __half* __restrict__ H2)
{
    const int b = blockIdx.x;                 // 0..383
    const int w = b >> 7;                     // which weight
    const float* W = w == 0 ? W0 : (w == 1 ? W1 : W2);
    __half* H = w == 0 ? H0 : (w == 1 ? H1 : H2);
    const int i = (b & 127) * 256 + threadIdx.x;   // 0..32767, 8 elems each
    float4 a = ((const float4*)W)[i * 2];
    float4 c = ((const float4*)W)[i * 2 + 1];
    uint4 u;
    u.x = pack_h2(a.x, a.y); u.y = pack_h2(a.z, a.w);
    u.z = pack_h2(c.x, c.y); u.w = pack_h2(c.z, c.w);
    ((uint4*)H)[i] = u;
}

// ---------------------------------------------------------------------------
// Fused q/k/v projection GEMM: BK=32, cp.async weights, register-staged A.
//   blockIdx.z: 0 -> q (split out), 1 -> k (split out), 2 -> v (plain out)
// 128x128 tile, 256 thr = 8 warps (4m x 2n), smem rows 32->40 halves (80B).
// __launch_bounds__(256,3): cap regs at 85 so 3 CTAs/SM fit (occupancy).
// ---------------------------------------------------------------------------
#define GK 512
#define BK32 32
#define NIT (GK/BK32)        /* 16 */
#define ROWB 80              /* bytes per smem row */
#define BUFB32 (128*ROWB)    /* 10240 */

__global__ __launch_bounds__(256, 3) void gemm_qkv(
    const float* __restrict__ qin, const float* __restrict__ kin,
    const float* __restrict__ vin,
    const __half* __restrict__ whq, const __half* __restrict__ whkv,
    const float* __restrict__ bq, const float* __restrict__ bkv,
    __half* __restrict__ qh, __half* __restrict__ ql,
    __half* __restrict__ kh, __half* __restrict__ kl,
    __half* __restrict__ vh)
{
    __shared__ __half As[2][128 * 40];
    __shared__ __half Bs[2][128 * 40];

    const int z = blockIdx.z;
    const float*  A    = z == 0 ? qin : (z == 1 ? kin : vin);
    const __half* W    = z == 0 ? whq : whkv;
    const float*  bias = z == 0 ? bq  : bkv;

    const int tid  = threadIdx.x;
    const int wid  = tid >> 5;
    const int lane = tid & 31;
    const int g    = lane >> 2;
    const int tig  = lane & 3;
    const int wm = wid & 3;
    const int wn = wid >> 2;
    const int row0 = blockIdx.y * 128;
    const int col0 = blockIdx.x * 128;

    const int lrow = tid >> 1;          // 0..127
    const int ke   = (tid & 1) * 16;    // half-element offset 0/16

    const float*  Ap = A + (size_t)(row0 + lrow) * GK + ke;
    const __half* Bp = W + (size_t)(col0 + lrow) * GK + ke;

    const uint32_t asb = smem_u32(As[0]);
    const uint32_t bsb = smem_u32(Bs[0]);
    const uint32_t sts_b = bsb + (uint32_t)(lrow * ROWB + ke * 2);
    const uint32_t aoff = (uint32_t)((wm * 32 + (lane & 15)) * ROWB + (lane >> 4) * 16);
    const uint32_t boff = (uint32_t)((wn * 64 + ((lane >> 4) << 3) + (lane & 7)) * ROWB
                                     + ((lane >> 3) & 1) * 16);

    float acc[2][8][4];
#pragma unroll
    for (int mt = 0; mt < 2; mt++)
#pragma unroll
        for (int nt = 0; nt < 8; nt++)
#pragma unroll
            for (int i = 0; i < 4; i++) acc[mt][nt][i] = 0.0f;

    float4 raf[4];
    auto ldgA = [&](int it) {
        const float* p = Ap + it * BK32;
        raf[0] = *(const float4*)(p + 0);
        raf[1] = *(const float4*)(p + 4);
        raf[2] = *(const float4*)(p + 8);
        raf[3] = *(const float4*)(p + 12);
    };
    auto stsA = [&](int buf) {
        uint4 u0, u1;
        u0.x = pack_h2(raf[0].x, raf[0].y); u0.y = pack_h2(raf[0].z, raf[0].w);
        u0.z = pack_h2(raf[1].x, raf[1].y); u0.w = pack_h2(raf[1].z, raf[1].w);
        u1.x = pack_h2(raf[2].x, raf[2].y); u1.y = pack_h2(raf[2].z, raf[2].w);
        u1.z = pack_h2(raf[3].x, raf[3].y); u1.w = pack_h2(raf[3].z, raf[3].w);
        *(uint4*)((char*)As[buf] + lrow * ROWB + ke * 2)      = u0;
        *(uint4*)((char*)As[buf] + lrow * ROWB + ke * 2 + 16) = u1;
    };
    auto cpaB = [&](int it, int buf) {
        const uint32_t d = sts_b + (uint32_t)buf * BUFB32;
        const __half* s = Bp + it * BK32;
        cp16(d, s);
        cp16(d + 16, s + 8);
    };

    // prologue
    cpaB(0, 0); CP_COMMIT();
    ldgA(0); stsA(0);
    cpaB(1, 1); CP_COMMIT();
    ldgA(1);
    CP_WAIT0();
    __syncthreads();

    for (int it = 0; it < NIT; it++) {
        const int cur = it & 1;
        if (it + 1 < NIT) stsA(cur ^ 1);
        if (it + 2 < NIT) ldgA(it + 2);

        const uint32_t ab = asb + (uint32_t)cur * BUFB32 + aoff;
        const uint32_t bb = bsb + (uint32_t)cur * BUFB32 + boff;
#pragma unroll
        for (int kg = 0; kg < 2; kg++) {
            uint32_t af[2][4];
            ldsm_x4(af[0], ab + kg * 32);
            ldsm_x4(af[1], ab + kg * 32 + 16 * ROWB);
#pragma unroll
            for (int p = 0; p < 4; p++) {
                uint32_t bf[4];
                ldsm_x4(bf, bb + (uint32_t)p * (16 * ROWB) + kg * 32);
                mma_f16(acc[0][2*p    ], af[0], &bf[0]);
                mma_f16(acc[0][2*p + 1], af[0], &bf[2]);
                mma_f16(acc[1][2*p    ], af[1], &bf[0]);
                mma_f16(acc[1][2*p + 1], af[1], &bf[2]);
            }
        }
        if (it + 1 < NIT) CP_WAIT0();
        __syncthreads();
        if (it + 2 < NIT) { cpaB(it + 2, cur); CP_COMMIT(); }
    }

    // epilogue
#pragma unroll
    for (int nt = 0; nt < 8; nt++) {
        const int col = col0 + wn * 64 + nt * 8 + tig * 2;
        const float bx = bias[col];
        const float by = bias[col + 1];
#pragma unroll
        for (int mt = 0; mt < 2; mt++) {
            const int r = row0 + wm * 32 + mt * 16 + g;
            const float v0x = acc[mt][nt][0] + bx, v0y = acc[mt][nt][1] + by;
            const float v1x = acc[mt][nt][2] + bx, v1y = acc[mt][nt][3] + by;
            if (z == 2) {
                *(uint32_t*)(vh + (size_t)r * D_ + col)       = pack_h2(v0x, v0y);
                *(uint32_t*)(vh + (size_t)(r + 8) * D_ + col) = pack_h2(v1x, v1y);
            } else {
                __half* Ch = z == 0 ? qh : kh;
                __half* Cl = z == 0 ? ql : kl;
                uint32_t h, l;
                split2h(v0x, v0y, h, l);
                *(uint32_t*)(Ch + (size_t)r * D_ + col) = h;
                *(uint32_t*)(Cl + (size_t)r * D_ + col) = l;
                split2h(v1x, v1y, h, l);
                *(uint32_t*)(Ch + (size_t)(r + 8) * D_ + col) = h;
                *(uint32_t*)(Cl + (size_t)(r + 8) * D_ + col) = l;
            }
        }
    }
}

// ---------------------------------------------------------------------------
// Final projection: A fp16 (attention out), cp.async both operands, fp32 out.
// __launch_bounds__(256,3) for 3 CTAs/SM.
// ---------------------------------------------------------------------------
__global__ __launch_bounds__(256, 3) void gemm_o(
    const __half* __restrict__ A, const __half* __restrict__ W,
    const float* __restrict__ bias, float* __restrict__ C)
{
    __shared__ __half As[2][128 * 40];
    __shared__ __half Bs[2][128 * 40];

    const int tid  = threadIdx.x;
    const int wid  = tid >> 5;
    const int lane = tid & 31;
    const int g    = lane >> 2;
    const int tig  = lane & 3;
    const int wm = wid & 3;
    const int wn = wid >> 2;
    const int row0 = blockIdx.y * 128;
    const int col0 = blockIdx.x * 128;
    const int N = D_;

    const int lrow = tid >> 1;
    const int ke   = (tid & 1) * 16;

    const __half* Ap = A + (size_t)(row0 + lrow) * GK + ke;
    const __half* Bp = W + (size_t)(col0 + lrow) * GK + ke;

    const uint32_t asb = smem_u32(As[0]);
    const uint32_t bsb = smem_u32(Bs[0]);
    const uint32_t sts_a = asb + (uint32_t)(lrow * ROWB + ke * 2);
    const uint32_t sts_b = bsb + (uint32_t)(lrow * ROWB + ke * 2);
    const uint32_t aoff = (uint32_t)((wm * 32 + (lane & 15)) * ROWB + (lane >> 4) * 16);
    const uint32_t boff = (uint32_t)((wn * 64 + ((lane >> 4) << 3) + (lane & 7)) * ROWB
                                     + ((lane >> 3) & 1) * 16);

    float acc[2][8][4];
#pragma unroll
    for (int mt = 0; mt < 2; mt++)
#pragma unroll
        for (int nt = 0; nt < 8; nt++)
#pragma unroll
            for (int i = 0; i < 4; i++) acc[mt][nt][i] = 0.0f;

    auto cpa = [&](int it, int buf) {
        const uint32_t da = sts_a + (uint32_t)buf * BUFB32;
        const uint32_t db = sts_b + (uint32_t)buf * BUFB32;
        const __half* sa = Ap + it * BK32;
        const __half* sb = Bp + it * BK32;
        cp16(da, sa); cp16(da + 16, sa + 8);
        cp16(db, sb); cp16(db + 16, sb + 8);
    };

    cpa(0, 0); CP_COMMIT();
    cpa(1, 1); CP_COMMIT();
    CP_WAIT0();
    __syncthreads();

    for (int it = 0; it < NIT; it++) {
        const int cur = it & 1;
        const uint32_t ab = asb + (uint32_t)cur * BUFB32 + aoff;
        const uint32_t bb = bsb + (uint32_t)cur * BUFB32 + boff;
#pragma unroll
        for (int kg = 0; kg < 2; kg++) {
            uint32_t af[2][4];
            ldsm_x4(af[0], ab + kg * 32);
            ldsm_x4(af[1], ab + kg * 32 + 16 * ROWB);
#pragma unroll
            for (int p = 0; p < 4; p++) {
                uint32_t bf[4];
                ldsm_x4(bf, bb + (uint32_t)p * (16 * ROWB) + kg * 32);
                mma_f16(acc[0][2*p    ], af[0], &bf[0]);
                mma_f16(acc[0][2*p + 1], af[0], &bf[2]);
                mma_f16(acc[1][2*p    ], af[1], &bf[0]);
                mma_f16(acc[1][2*p + 1], af[1], &bf[2]);
            }
        }
        if (it + 1 < NIT) CP_WAIT0();
        __syncthreads();
        if (it + 2 < NIT) { cpa(it + 2, cur); CP_COMMIT(); }
    }

#pragma unroll
    for (int nt = 0; nt < 8; nt++) {
        const int col = col0 + wn * 64 + nt * 8 + tig * 2;
        const float bx = bias[col];
        const float by = bias[col + 1];
#pragma unroll
        for (int mt = 0; mt < 2; mt++) {
            const int r = row0 + wm * 32 + mt * 16 + g;
            float2 a; a.x = acc[mt][nt][0] + bx; a.y = acc[mt][nt][1] + by;
            float2 b; b.x = acc[mt][nt][2] + bx; b.y = acc[mt][nt][3] + by;
            *(float2*)(C + (size_t)r * N + col)       = a;
            *(float2*)(C + (size_t)(r + 8) * N + col) = b;
        }
    }
}

// ---------------------------------------------------------------------------
// fp16 attention (unchanged from passing R12 kernel)
// ---------------------------------------------------------------------------
#define P1_BUF   30720
#define QH_O     0
#define QL_O     3072
#define KH_O     6144
#define KL_O     18432
#define PH_O     0
#define P_ROW_B  528
#define VH_O     33792
#define V_BUF    8448
#define V_ROW_B  528
#define RED_O    50688
#define ATTN_SMEM 61440

__global__ __launch_bounds__(256) void attn_f16_kernel(
    const __half* __restrict__ qh, const __half* __restrict__ ql,
    const __half* __restrict__ kh, const __half* __restrict__ kl,
    const __half* __restrict__ vh, __half* __restrict__ o)
{
    extern __shared__ char smc[];
    const int tid  = threadIdx.x;
    const int wid  = tid >> 5;
    const int lane = tid & 31;
    const int g    = lane >> 2;
    const int tig  = lane & 3;
    const int wm   = wid & 3;
    const int wn   = wid >> 2;

    const int bl = blockIdx.x >> 2;
    const int ct = blockIdx.x & 3;

    const size_t qoff = (size_t)(bl * C_ + ct * 64) * D_;
    const size_t koff = (size_t)bl * S_ * D_;
    const __half* Vb = vh + koff;

    const uint32_t smb = smem_u32(smc);
    const uint32_t qa  = (uint32_t)((wm * 16 + (lane & 15)) * 48 + (lane >> 4) * 16);
    const uint32_t kb_ = (uint32_t)((wn * 128 + ((lane >> 4) << 3) + (lane & 7)) * 48
                                    + ((lane >> 3) & 1) * 16);
    const uint32_t pa  = (uint32_t)((wm * 16 + (lane & 15)) * P_ROW_B + (lane >> 4) * 16);
    const uint32_t va  = (uint32_t)(((((lane >> 3) & 1) * 8 + (lane & 7)) * V_ROW_B)
                                    + (lane >> 4) * 16 + wn * 256);

    float acc[16][4];
#pragma unroll
    for (int nt = 0; nt < 16; nt++)
#pragma unroll
        for (int i = 0; i < 4; i++) acc[nt][i] = 0.0f;

    const int qrow = tid >> 2;
    const int kc   = (tid & 3) * 4;

    uint2 rqh, rql, rkh[4], rkl[4];
    auto ldg1 = [&](int it) {
        const int k0 = it * 16 + kc;
        rqh = *(const uint2*)(qh + qoff + (size_t)qrow * D_ + k0);
        rql = *(const uint2*)(ql + qoff + (size_t)qrow * D_ + k0);
#pragma unroll
        for (int i = 0; i < 4; i++) {
            const size_t r = koff + (size_t)(qrow + i * 64) * D_ + k0;
            rkh[i] = *(const uint2*)(kh + r);
            rkl[i] = *(const uint2*)(kl + r);
        }
    };
    auto sts1 = [&](int b) {
        char* base = smc + b * P1_BUF;
        *(uint2*)(base + QH_O + qrow * 48 + kc * 2) = rqh;
        *(uint2*)(base + QL_O + qrow * 48 + kc * 2) = rql;
#pragma unroll
        for (int i = 0; i < 4; i++) {
            *(uint2*)(base + KH_O + (qrow + i * 64) * 48 + kc * 2) = rkh[i];
            *(uint2*)(base + KL_O + (qrow + i * 64) * 48 + kc * 2) = rkl[i];
        }
    };

    ldg1(0); sts1(0); ldg1(1);
    __syncthreads();

    for (int it = 0; it < D_ / 16; it++) {
        const int cur = it & 1;
        if (it + 1 < D_ / 16) sts1(cur ^ 1);
        if (it + 2 < D_ / 16) ldg1(it + 2);

        const uint32_t bufb = smb + (uint32_t)cur * P1_BUF;
        uint32_t ah[4], al[4];
        ldsm_x4(ah, bufb + QH_O + qa);
        ldsm_x4(al, bufb + QL_O + qa);
#pragma unroll
        for (int p = 0; p < 8; p++) {
            uint32_t bh[4], blo[4];
            ldsm_x4(bh,  bufb + KH_O + kb_ + (uint32_t)p * 768);
            ldsm_x4(blo, bufb + KL_O + kb_ + (uint32_t)p * 768);
            mma_f16(acc[2*p    ], ah, &blo[0]);
            mma_f16(acc[2*p    ], al, &bh[0]);
            mma_f16(acc[2*p    ], ah, &bh[0]);
            mma_f16(acc[2*p + 1], ah, &blo[2]);
            mma_f16(acc[2*p + 1], al, &bh[2]);
            mma_f16(acc[2*p + 1], ah, &bh[2]);
        }
        __syncthreads();
    }

    {
        float* redm = (float*)(smc + RED_O);
        float* reds = redm + 128;
        const float scale = 0.04419417382415922f;
        const int r0 = wm * 16 + g;

        float mx0 = -1e30f, mx1 = -1e30f;
#pragma unroll
        for (int nt = 0; nt < 16; nt++) {
            acc[nt][0] *= scale; acc[nt][1] *= scale;
            acc[nt][2] *= scale; acc[nt][3] *= scale;
            mx0 = fmaxf(mx0, fmaxf(acc[nt][0], acc[nt][1]));
            mx1 = fmaxf(mx1, fmaxf(acc[nt][2], acc[nt][3]));
        }
        mx0 = fmaxf(mx0, __shfl_xor_sync(0xffffffffu, mx0, 1));
        mx0 = fmaxf(mx0, __shfl_xor_sync(0xffffffffu, mx0, 2));
        mx1 = fmaxf(mx1, __shfl_xor_sync(0xffffffffu, mx1, 1));
        mx1 = fmaxf(mx1, __shfl_xor_sync(0xffffffffu, mx1, 2));
        if (tig == 0) { redm[r0 * 2 + wn] = mx0; redm[(r0 + 8) * 2 + wn] = mx1; }
        __syncthreads();
        const float m0 = fmaxf(redm[r0 * 2], redm[r0 * 2 + 1]);
        const float m1 = fmaxf(redm[(r0 + 8) * 2], redm[(r0 + 8) * 2 + 1]);

        float s0 = 0.0f, s1 = 0.0f;
#pragma unroll
        for (int nt = 0; nt < 16; nt++) {
            acc[nt][0] = __expf(acc[nt][0] - m0); s0 += acc[nt][0];
            acc[nt][1] = __expf(acc[nt][1] - m0); s0 += acc[nt][1];
            acc[nt][2] = __expf(acc[nt][2] - m1); s1 += acc[nt][2];
            acc[nt][3] = __expf(acc[nt][3] - m1); s1 += acc[nt][3];
        }
        s0 += __shfl_xor_sync(0xffffffffu, s0, 1);
        s0 += __shfl_xor_sync(0xffffffffu, s0, 2);
        s1 += __shfl_xor_sync(0xffffffffu, s1, 1);
        s1 += __shfl_xor_sync(0xffffffffu, s1, 2);
        if (tig == 0) { reds[r0 * 2 + wn] = s0; reds[(r0 + 8) * 2 + wn] = s1; }
        __syncthreads();
        const float inv0 = 1.0f / (reds[r0 * 2] + reds[r0 * 2 + 1]);
        const float inv1 = 1.0f / (reds[(r0 + 8) * 2] + reds[(r0 + 8) * 2 + 1]);

#pragma unroll
        for (int nt = 0; nt < 16; nt++) {
            const int col = wn * 128 + nt * 8 + tig * 2;
            *(uint32_t*)(smc + PH_O + r0 * P_ROW_B + col * 2) =
                pack_h2(acc[nt][0] * inv0, acc[nt][1] * inv0);
            *(uint32_t*)(smc + PH_O + (r0 + 8) * P_ROW_B + col * 2) =
                pack_h2(acc[nt][2] * inv1, acc[nt][3] * inv1);
        }
    }
    __syncthreads();

    const int vrow = tid >> 5;
    const int vc16 = (tid & 31);
    __half* ob = o + qoff;

    uint4 rv0, rv1;
    auto ldgv = [&](int ci) {
        const int s0 = (ci & 15) * 16;
        const int hh = ci >> 4;
        rv0 = *(const uint4*)(Vb + (size_t)(s0 + vrow) * D_ + hh * 256 + vc16 * 8);
        rv1 = *(const uint4*)(Vb + (size_t)(s0 + vrow + 8) * D_ + hh * 256 + vc16 * 8);
    };
    auto stsv = [&](int b) {
        char* base = smc + VH_O + b * V_BUF;
        *(uint4*)(base + vrow * V_ROW_B + vc16 * 16) = rv0;
        *(uint4*)(base + (vrow + 8) * V_ROW_B + vc16 * 16) = rv1;
    };

    for (int h = 0; h < 2; h++) {
        float oacc[16][4];
#pragma unroll
        for (int nt = 0; nt < 16; nt++)
#pragma unroll
            for (int i = 0; i < 4; i++) oacc[nt][i] = 0.0f;

        ldgv(h * 16); stsv(0); ldgv(h * 16 + 1);
        __syncthreads();

        for (int j = 0; j < 16; j++) {
            const int cur = j & 1;
            if (j + 1 < 16) stsv(cur ^ 1);
            if (j + 2 < 16) ldgv(h * 16 + j + 2);

            uint32_t af[4];
            ldsm_x4(af, smb + PH_O + pa + (uint32_t)j * 32);
            const uint32_t vb_ = smb + VH_O + (uint32_t)cur * V_BUF + va;
#pragma unroll
            for (int p = 0; p < 8; p++) {
                uint32_t bf[4];
                ldsm_x4_t(bf, vb_ + (uint32_t)p * 32);
                mma_f16(oacc[2*p    ], af, &bf[0]);
                mma_f16(oacc[2*p + 1], af, &bf[2]);
            }
            __syncthreads();
        }

#pragma unroll
        for (int nt = 0; nt < 16; nt++) {
            const int col = h * 256 + wn * 128 + nt * 8 + tig * 2;
            const int r0  = wm * 16 + g;
            *(uint32_t*)(ob + (size_t)r0 * D_ + col) =
                pack_h2(oacc[nt][0], oacc[nt][1]);
            *(uint32_t*)(ob + (size_t)(r0 + 8) * D_ + col) =
                pack_h2(oacc[nt][2], oacc[nt][3]);
        }
    }
}

// ---------------------------------------------------------------------------
extern "C" void kernel_launch(void* const* d_in, const int* in_sizes, int n_in,
                              void* d_out, int out_size)
{
    (void)in_sizes; (void)n_in; (void)out_size;
    const float* queries = (const float*)d_in[0];
    const float* keys    = (const float*)d_in[1];
    const float* values  = (const float*)d_in[2];
    const float* Wq      = (const float*)d_in[3];
    const float* bq      = (const float*)d_in[4];
    const float* Wkv     = (const float*)d_in[5];
    const float* bkv     = (const float*)d_in[6];
    const float* Wo      = (const float*)d_in[7];
    const float* bo      = (const float*)d_in[8];
    float* out = (float*)d_out;

    __half *qh, *ql, *kh, *kl, *vh, *oh, *whq, *whkv, *who;
    cudaGetSymbolAddress((void**)&qh,   g_qh);
    cudaGetSymbolAddress((void**)&ql,   g_ql);
    cudaGetSymbolAddress((void**)&kh,   g_kh);
    cudaGetSymbolAddress((void**)&kl,   g_kl);
    cudaGetSymbolAddress((void**)&vh,   g_vh);
    cudaGetSymbolAddress((void**)&oh,   g_oh);
    cudaGetSymbolAddress((void**)&whq,  g_whq);
    cudaGetSymbolAddress((void**)&whkv, g_whkv);
    cudaGetSymbolAddress((void**)&who,  g_who);

    (void)cudaFuncSetAttribute(attn_f16_kernel,
                               cudaFuncAttributeMaxDynamicSharedMemorySize,
                               ATTN_SMEM);

    // Weights -> fp16 (one launch)
    convert_w3<<<384, 256>>>(Wq, whq, Wkv, whkv, Wo, who);

    // Fused q/k/v projections
    dim3 gqkv(D_ / 128, NQ / 128, 3);   // (4, 256, 3)
    gemm_qkv<<<gqkv, 256>>>(queries, keys, values, whq, whkv, bq, bkv,
                            qh, ql, kh, kl, vh);

    // Attention
    attn_f16_kernel<<<B_ * L_ * (C_ / 64), 256, ATTN_SMEM>>>(qh, ql, kh, kl, vh, oh);

    // Output projection
    dim3 go(D_ / 128, NQ / 128);        // (4, 256)
    gemm_o<<<go, 256>>>(oh, who, bo, out);
}

// round 16
// speedup vs baseline: 1.5324x; 1.5324x over previous
#include <cuda_runtime.h>
#include <cuda_fp16.h>
#include <math.h>
#include <stdint.h>

#define B_ 2
#define L_ 64
#define C_ 256
#define S_ 256
#define D_ 512
#define NQ (B_*L_*C_)   /* 32768 rows */

// fp16 pipeline scratch
__device__ __half g_aq[(size_t)NQ * D_];
__device__ __half g_ak[(size_t)NQ * D_];
__device__ __half g_av[(size_t)NQ * D_];
__device__ __half g_qh[(size_t)NQ * D_];
__device__ __half g_ql[(size_t)NQ * D_];
__device__ __half g_kh[(size_t)NQ * D_];
__device__ __half g_kl[(size_t)NQ * D_];
__device__ __half g_vh[(size_t)NQ * D_];
__device__ __half g_oh[(size_t)NQ * D_];
__device__ __half g_whq [(size_t)D_ * D_];
__device__ __half g_whkv[(size_t)D_ * D_];
__device__ __half g_who [(size_t)D_ * D_];

// ---------------------------------------------------------------------------
// helpers
// ---------------------------------------------------------------------------
__device__ __forceinline__ uint32_t smem_u32(const void* p) {
    uint32_t a;
    asm("{ .reg .u64 t; cvta.to.shared.u64 t, %1; cvt.u32.u64 %0, t; }"
        : "=r"(a) : "l"(p));
    return a;
}
__device__ __forceinline__ uint32_t pack_h2(float a, float b) {
    __half2 h = __floats2half2_rn(a, b);
    return *(uint32_t*)&h;
}
__device__ __forceinline__ void split2h(float a, float b, uint32_t& h, uint32_t& l) {
    __half ha = __float2half_rn(a);
    __half hb = __float2half_rn(b);
    __half la = __float2half_rn(a - __half2float(ha));
    __half lb = __float2half_rn(b - __half2float(hb));
    __half2 hp = __halves2half2(ha, hb);
    __half2 lp = __halves2half2(la, lb);
    h = *(uint32_t*)&hp;
    l = *(uint32_t*)&lp;
}
__device__ __forceinline__ void mma_f16(float d[4], const uint32_t a[4],
                                        const uint32_t b[2]) {
    asm volatile(
        "mma.sync.aligned.m16n8k16.row.col.f32.f16.f16.f32 "
        "{%0,%1,%2,%3}, {%4,%5,%6,%7}, {%8,%9}, {%0,%1,%2,%3};\n"
        : "+f"(d[0]), "+f"(d[1]), "+f"(d[2]), "+f"(d[3])
        : "r"(a[0]), "r"(a[1]), "r"(a[2]), "r"(a[3]),
          "r"(b[0]), "r"(b[1]));
}
__device__ __forceinline__ void ldsm_x4(uint32_t r[4], uint32_t addr) {
    asm volatile("ldmatrix.sync.aligned.m8n8.x4.shared.b16 {%0,%1,%2,%3}, [%4];"
        : "=r"(r[0]), "=r"(r[1]), "=r"(r[2]), "=r"(r[3]) : "r"(addr));
}
__device__ __forceinline__ void ldsm_x4_t(uint32_t r[4], uint32_t addr) {
    asm volatile("ldmatrix.sync.aligned.m8n8.x4.trans.shared.b16 {%0,%1,%2,%3}, [%4];"
        : "=r"(r[0]), "=r"(r[1]), "=r"(r[2]), "=r"(r[3]) : "r"(addr));
}
__device__ __forceinline__ void cp16(uint32_t smem_dst, const void* gptr) {
    asm volatile("cp.async.ca.shared.global [%0], [%1], 16;"
                 :: "r"(smem_dst), "l"(gptr));
}
#define CP_COMMIT() asm volatile("cp.async.commit_group;" ::: "memory")
#define CP_WAIT0()  asm volatile("cp.async.wait_group 0;" ::: "memory")
#define CP_WAIT1()  asm volatile("cp.async.wait_group 1;" ::: "memory")

// ---------------------------------------------------------------------------
// Converters
// ---------------------------------------------------------------------------
__global__ __launch_bounds__(256) void convert_w3(
    const float* __restrict__ W0, __half* __restrict__ H0,
    const float* __restrict__ W1, __half* __restrict__ H1,
    const float* __restrict__ W2, __half* __restrict__ H2)
{
    const int b = blockIdx.x;                 // 0..383
    const int w = b >> 7;
    const float* W = w == 0 ? W0 : (w == 1 ? W1 : W2);
    __half* H = w == 0 ? H0 : (w == 1 ? H1 : H2);
    const int i = (b & 127) * 256 + threadIdx.x;
    float4 a = ((const float4*)W)[i * 2];
    float4 c = ((const float4*)W)[i * 2 + 1];
    uint4 u;
    u.x = pack_h2(a.x, a.y); u.y = pack_h2(a.z, a.w);
    u.z = pack_h2(c.x, c.y); u.w = pack_h2(c.z, c.w);
    ((uint4*)H)[i] = u;
}

// q/k/v input fp32 -> fp16 (NQ*D each)
__global__ __launch_bounds__(256) void convert_a3(
    const float* __restrict__ A0, __half* __restrict__ H0,
    const float* __restrict__ A1, __half* __restrict__ H1,
    const float* __restrict__ A2, __half* __restrict__ H2)
{
    const int b = blockIdx.x;                 // 0..24575
    const int w = b >> 13;                    // 8192 blocks per input
    const float* A = w == 0 ? A0 : (w == 1 ? A1 : A2);
    __half* H = w == 0 ? H0 : (w == 1 ? H1 : H2);
    const int i = (b & 8191) * 256 + threadIdx.x;   // 8 floats each
    float4 a = ((const float4*)A)[i * 2];
    float4 c = ((const float4*)A)[i * 2 + 1];
    uint4 u;
    u.x = pack_h2(a.x, a.y); u.y = pack_h2(a.z, a.w);
    u.z = pack_h2(c.x, c.y); u.w = pack_h2(c.z, c.w);
    ((uint4*)H)[i] = u;
}

// ---------------------------------------------------------------------------
// BK=64 fp16 GEMM core constants
//   smem rows: 64 halves padded to 88 (176 B) -> conflict-free ldmatrix
//   per stage: A 128*176 + B 128*176 = 45056 B; 2 stages = 90112 B dynamic
// ---------------------------------------------------------------------------
#define GK 512
#define BK64 64
#define NIT64 (GK/BK64)      /* 8 */
#define ROWB64 176
#define ABUF   22528
#define STAGEB 45056
#define GEMM_SMEM (2*STAGEB) /* 90112 */

// ---------------------------------------------------------------------------
// Fused q/k/v projection: all-fp16 inputs, cp.async both operands.
//   blockIdx.z: 0 -> q (split out), 1 -> k (split out), 2 -> v (plain out)
// ---------------------------------------------------------------------------
__global__ __launch_bounds__(256) void gemm_qkv(
    const __half* __restrict__ aq, const __half* __restrict__ ak,
    const __half* __restrict__ av,
    const __half* __restrict__ whq, const __half* __restrict__ whkv,
    const float* __restrict__ bq, const float* __restrict__ bkv,
    __half* __restrict__ qh, __half* __restrict__ ql,
    __half* __restrict__ kh, __half* __restrict__ kl,
    __half* __restrict__ vh)
{
    extern __shared__ char smem[];
    const int z = blockIdx.z;
    const __half* A    = z == 0 ? aq : (z == 1 ? ak : av);
    const __half* W    = z == 0 ? whq : whkv;
    const float*  bias = z == 0 ? bq  : bkv;

    const int tid  = threadIdx.x;
    const int wid  = tid >> 5;
    const int lane = tid & 31;
    const int g    = lane >> 2;
    const int tig  = lane & 3;
    const int wm = wid & 3;
    const int wn = wid >> 2;
    const int row0 = blockIdx.y * 128;
    const int col0 = blockIdx.x * 128;

    const int lrow = tid >> 1;          // 0..127
    const int keh  = (tid & 1) * 32;    // half-elem offset 0/32

    const __half* Ap = A + (size_t)(row0 + lrow) * GK + keh;
    const __half* Bp = W + (size_t)(col0 + lrow) * GK + keh;

    const uint32_t smb = smem_u32(smem);
    const uint32_t sts_a = smb + (uint32_t)(lrow * ROWB64 + keh * 2);
    const uint32_t sts_b = sts_a + ABUF;
    const uint32_t aoff = (uint32_t)((wm * 32 + (lane & 15)) * ROWB64 + (lane >> 4) * 16);
    const uint32_t boff = (uint32_t)((wn * 64 + ((lane >> 4) << 3) + (lane & 7)) * ROWB64
                                     + ((lane >> 3) & 1) * 16);

    float acc[2][8][4];
#pragma unroll
    for (int mt = 0; mt < 2; mt++)
#pragma unroll
        for (int nt = 0; nt < 8; nt++)
#pragma unroll
            for (int i = 0; i < 4; i++) acc[mt][nt][i] = 0.0f;

    auto cpa = [&](int it, int buf) {
        const uint32_t da = sts_a + (uint32_t)buf * STAGEB;
        const uint32_t db = sts_b + (uint32_t)buf * STAGEB;
        const __half* sa = Ap + it * BK64;
        const __half* sb = Bp + it * BK64;
        cp16(da,      sa);      cp16(da + 16, sa + 8);
        cp16(da + 32, sa + 16); cp16(da + 48, sa + 24);
        cp16(db,      sb);      cp16(db + 16, sb + 8);
        cp16(db + 32, sb + 16); cp16(db + 48, sb + 24);
    };

    cpa(0, 0); CP_COMMIT();
    cpa(1, 1); CP_COMMIT();
    CP_WAIT1();
    __syncthreads();

    for (int it = 0; it < NIT64; it++) {
        const int cur = it & 1;
        const uint32_t ab = smb + (uint32_t)cur * STAGEB + aoff;
        const uint32_t bb = smb + (uint32_t)cur * STAGEB + ABUF + boff;
#pragma unroll
        for (int kg = 0; kg < 4; kg++) {
            uint32_t af[2][4];
            ldsm_x4(af[0], ab + kg * 32);
            ldsm_x4(af[1], ab + kg * 32 + 16 * ROWB64);
#pragma unroll
            for (int p = 0; p < 4; p++) {
                uint32_t bf[4];
                ldsm_x4(bf, bb + (uint32_t)p * (16 * ROWB64) + kg * 32);
                mma_f16(acc[0][2*p    ], af[0], &bf[0]);
                mma_f16(acc[0][2*p + 1], af[0], &bf[2]);
                mma_f16(acc[1][2*p    ], af[1], &bf[0]);
                mma_f16(acc[1][2*p + 1], af[1], &bf[2]);
            }
        }
        if (it + 1 < NIT64) CP_WAIT0();
        __syncthreads();
        if (it + 2 < NIT64) { cpa(it + 2, cur); CP_COMMIT(); }
    }

    // epilogue
#pragma unroll
    for (int nt = 0; nt < 8; nt++) {
        const int col = col0 + wn * 64 + nt * 8 + tig * 2;
        const float bx = bias[col];
        const float by = bias[col + 1];
#pragma unroll
        for (int mt = 0; mt < 2; mt++) {
            const int r = row0 + wm * 32 + mt * 16 + g;
            const float v0x = acc[mt][nt][0] + bx, v0y = acc[mt][nt][1] + by;
            const float v1x = acc[mt][nt][2] + bx, v1y = acc[mt][nt][3] + by;
            if (z == 2) {
                *(uint32_t*)(vh + (size_t)r * D_ + col)       = pack_h2(v0x, v0y);
                *(uint32_t*)(vh + (size_t)(r + 8) * D_ + col) = pack_h2(v1x, v1y);
            } else {
                __half* Ch = z == 0 ? qh : kh;
                __half* Cl = z == 0 ? ql : kl;
                uint32_t h, l;
                split2h(v0x, v0y, h, l);
                *(uint32_t*)(Ch + (size_t)r * D_ + col) = h;
                *(uint32_t*)(Cl + (size_t)r * D_ + col) = l;
                split2h(v1x, v1y, h, l);
                *(uint32_t*)(Ch + (size_t)(r + 8) * D_ + col) = h;
                *(uint32_t*)(Cl + (size_t)(r + 8) * D_ + col) = l;
            }
        }
    }
}

// ---------------------------------------------------------------------------
// Final projection: A fp16 (attention out), BK=64, fp32 out.
// ---------------------------------------------------------------------------
__global__ __launch_bounds__(256) void gemm_o(
    const __half* __restrict__ A, const __half* __restrict__ W,
    const float* __restrict__ bias, float* __restrict__ C)
{
    extern __shared__ char smem[];
    const int tid  = threadIdx.x;
    const int wid  = tid >> 5;
    const int lane = tid & 31;
    const int g    = lane >> 2;
    const int tig  = lane & 3;
    const int wm = wid & 3;
    const int wn = wid >> 2;
    const int row0 = blockIdx.y * 128;
    const int col0 = blockIdx.x * 128;
    const int N = D_;

    const int lrow = tid >> 1;
    const int keh  = (tid & 1) * 32;

    const __half* Ap = A + (size_t)(row0 + lrow) * GK + keh;
    const __half* Bp = W + (size_t)(col0 + lrow) * GK + keh;

    const uint32_t smb = smem_u32(smem);
    const uint32_t sts_a = smb + (uint32_t)(lrow * ROWB64 + keh * 2);
    const uint32_t sts_b = sts_a + ABUF;
    const uint32_t aoff = (uint32_t)((wm * 32 + (lane & 15)) * ROWB64 + (lane >> 4) * 16);
    const uint32_t boff = (uint32_t)((wn * 64 + ((lane >> 4) << 3) + (lane & 7)) * ROWB64
                                     + ((lane >> 3) & 1) * 16);

    float acc[2][8][4];
#pragma unroll
    for (int mt = 0; mt < 2; mt++)
#pragma unroll
        for (int nt = 0; nt < 8; nt++)
#pragma unroll
            for (int i = 0; i < 4; i++) acc[mt][nt][i] = 0.0f;

    auto cpa = [&](int it, int buf) {
        const uint32_t da = sts_a + (uint32_t)buf * STAGEB;
        const uint32_t db = sts_b + (uint32_t)buf * STAGEB;
        const __half* sa = Ap + it * BK64;
        const __half* sb = Bp + it * BK64;
        cp16(da,      sa);      cp16(da + 16, sa + 8);
        cp16(da + 32, sa + 16); cp16(da + 48, sa + 24);
        cp16(db,      sb);      cp16(db + 16, sb + 8);
        cp16(db + 32, sb + 16); cp16(db + 48, sb + 24);
    };

    cpa(0, 0); CP_COMMIT();
    cpa(1, 1); CP_COMMIT();
    CP_WAIT1();
    __syncthreads();

    for (int it = 0; it < NIT64; it++) {
        const int cur = it & 1;
        const uint32_t ab = smb + (uint32_t)cur * STAGEB + aoff;
        const uint32_t bb = smb + (uint32_t)cur * STAGEB + ABUF + boff;
#pragma unroll
        for (int kg = 0; kg < 4; kg++) {
            uint32_t af[2][4];
            ldsm_x4(af[0], ab + kg * 32);
            ldsm_x4(af[1], ab + kg * 32 + 16 * ROWB64);
#pragma unroll
            for (int p = 0; p < 4; p++) {
                uint32_t bf[4];
                ldsm_x4(bf, bb + (uint32_t)p * (16 * ROWB64) + kg * 32);
                mma_f16(acc[0][2*p    ], af[0], &bf[0]);
                mma_f16(acc[0][2*p + 1], af[0], &bf[2]);
                mma_f16(acc[1][2*p    ], af[1], &bf[0]);
                mma_f16(acc[1][2*p + 1], af[1], &bf[2]);
            }
        }
        if (it + 1 < NIT64) CP_WAIT0();
        __syncthreads();
        if (it + 2 < NIT64) { cpa(it + 2, cur); CP_COMMIT(); }
    }

#pragma unroll
    for (int nt = 0; nt < 8; nt++) {
        const int col = col0 + wn * 64 + nt * 8 + tig * 2;
        const float bx = bias[col];
        const float by = bias[col + 1];
#pragma unroll
        for (int mt = 0; mt < 2; mt++) {
            const int r = row0 + wm * 32 + mt * 16 + g;
            float2 a; a.x = acc[mt][nt][0] + bx; a.y = acc[mt][nt][1] + by;
            float2 b; b.x = acc[mt][nt][2] + bx; b.y = acc[mt][nt][3] + by;
            *(float2*)(C + (size_t)r * N + col)       = a;
            *(float2*)(C + (size_t)(r + 8) * N + col) = b;
        }
    }
}

// ---------------------------------------------------------------------------
// fp16 attention (unchanged from passing R12 kernel)
// ---------------------------------------------------------------------------
#define P1_BUF   30720
#define QH_O     0
#define QL_O     3072
#define KH_O     6144
#define KL_O     18432
#define PH_O     0
#define P_ROW_B  528
#define VH_O     33792
#define V_BUF    8448
#define V_ROW_B  528
#define RED_O    50688
#define ATTN_SMEM 61440

__global__ __launch_bounds__(256) void attn_f16_kernel(
    const __half* __restrict__ qh, const __half* __restrict__ ql,
    const __half* __restrict__ kh, const __half* __restrict__ kl,
    const __half* __restrict__ vh, __half* __restrict__ o)
{
    extern __shared__ char smc[];
    const int tid  = threadIdx.x;
    const int wid  = tid >> 5;
    const int lane = tid & 31;
    const int g    = lane >> 2;
    const int tig  = lane & 3;
    const int wm   = wid & 3;
    const int wn   = wid >> 2;

    const int bl = blockIdx.x >> 2;
    const int ct = blockIdx.x & 3;

    const size_t qoff = (size_t)(bl * C_ + ct * 64) * D_;
    const size_t koff = (size_t)bl * S_ * D_;
    const __half* Vb = vh + koff;

    const uint32_t smb = smem_u32(smc);
    const uint32_t qa  = (uint32_t)((wm * 16 + (lane & 15)) * 48 + (lane >> 4) * 16);
    const uint32_t kb_ = (uint32_t)((wn * 128 + ((lane >> 4) << 3) + (lane & 7)) * 48
                                    + ((lane >> 3) & 1) * 16);
    const uint32_t pa  = (uint32_t)((wm * 16 + (lane & 15)) * P_ROW_B + (lane >> 4) * 16);
    const uint32_t va  = (uint32_t)(((((lane >> 3) & 1) * 8 + (lane & 7)) * V_ROW_B)
                                    + (lane >> 4) * 16 + wn * 256);

    float acc[16][4];
#pragma unroll
    for (int nt = 0; nt < 16; nt++)
#pragma unroll
        for (int i = 0; i < 4; i++) acc[nt][i] = 0.0f;

    const int qrow = tid >> 2;
    const int kc   = (tid & 3) * 4;

    uint2 rqh, rql, rkh[4], rkl[4];
    auto ldg1 = [&](int it) {
        const int k0 = it * 16 + kc;
        rqh = *(const uint2*)(qh + qoff + (size_t)qrow * D_ + k0);
        rql = *(const uint2*)(ql + qoff + (size_t)qrow * D_ + k0);
#pragma unroll
        for (int i = 0; i < 4; i++) {
            const size_t r = koff + (size_t)(qrow + i * 64) * D_ + k0;
            rkh[i] = *(const uint2*)(kh + r);
            rkl[i] = *(const uint2*)(kl + r);
        }
    };
    auto sts1 = [&](int b) {
        char* base = smc + b * P1_BUF;
        *(uint2*)(base + QH_O + qrow * 48 + kc * 2) = rqh;
        *(uint2*)(base + QL_O + qrow * 48 + kc * 2) = rql;
#pragma unroll
        for (int i = 0; i < 4; i++) {
            *(uint2*)(base + KH_O + (qrow + i * 64) * 48 + kc * 2) = rkh[i];
            *(uint2*)(base + KL_O + (qrow + i * 64) * 48 + kc * 2) = rkl[i];
        }
    };

    ldg1(0); sts1(0); ldg1(1);
    __syncthreads();

    for (int it = 0; it < D_ / 16; it++) {
        const int cur = it & 1;
        if (it + 1 < D_ / 16) sts1(cur ^ 1);
        if (it + 2 < D_ / 16) ldg1(it + 2);

        const uint32_t bufb = smb + (uint32_t)cur * P1_BUF;
        uint32_t ah[4], al[4];
        ldsm_x4(ah, bufb + QH_O + qa);
        ldsm_x4(al, bufb + QL_O + qa);
#pragma unroll
        for (int p = 0; p < 8; p++) {
            uint32_t bh[4], blo[4];
            ldsm_x4(bh,  bufb + KH_O + kb_ + (uint32_t)p * 768);
            ldsm_x4(blo, bufb + KL_O + kb_ + (uint32_t)p * 768);
            mma_f16(acc[2*p    ], ah, &blo[0]);
            mma_f16(acc[2*p    ], al, &bh[0]);
            mma_f16(acc[2*p    ], ah, &bh[0]);
            mma_f16(acc[2*p + 1], ah, &blo[2]);
            mma_f16(acc[2*p + 1], al, &bh[2]);
            mma_f16(acc[2*p + 1], ah, &bh[2]);
        }
        __syncthreads();
    }

    {
        float* redm = (float*)(smc + RED_O);
        float* reds = redm + 128;
        const float scale = 0.04419417382415922f;
        const int r0 = wm * 16 + g;

        float mx0 = -1e30f, mx1 = -1e30f;
#pragma unroll
        for (int nt = 0; nt < 16; nt++) {
            acc[nt][0] *= scale; acc[nt][1] *= scale;
            acc[nt][2] *= scale; acc[nt][3] *= scale;
            mx0 = fmaxf(mx0, fmaxf(acc[nt][0], acc[nt][1]));
            mx1 = fmaxf(mx1, fmaxf(acc[nt][2], acc[nt][3]));
        }
        mx0 = fmaxf(mx0, __shfl_xor_sync(0xffffffffu, mx0, 1));
        mx0 = fmaxf(mx0, __shfl_xor_sync(0xffffffffu, mx0, 2));
        mx1 = fmaxf(mx1, __shfl_xor_sync(0xffffffffu, mx1, 1));
        mx1 = fmaxf(mx1, __shfl_xor_sync(0xffffffffu, mx1, 2));
        if (tig == 0) { redm[r0 * 2 + wn] = mx0; redm[(r0 + 8) * 2 + wn] = mx1; }
        __syncthreads();
        const float m0 = fmaxf(redm[r0 * 2], redm[r0 * 2 + 1]);
        const float m1 = fmaxf(redm[(r0 + 8) * 2], redm[(r0 + 8) * 2 + 1]);

        float s0 = 0.0f, s1 = 0.0f;
#pragma unroll
        for (int nt = 0; nt < 16; nt++) {
            acc[nt][0] = __expf(acc[nt][0] - m0); s0 += acc[nt][0];
            acc[nt][1] = __expf(acc[nt][1] - m0); s0 += acc[nt][1];
            acc[nt][2] = __expf(acc[nt][2] - m1); s1 += acc[nt][2];
            acc[nt][3] = __expf(acc[nt][3] - m1); s1 += acc[nt][3];
        }
        s0 += __shfl_xor_sync(0xffffffffu, s0, 1);
        s0 += __shfl_xor_sync(0xffffffffu, s0, 2);
        s1 += __shfl_xor_sync(0xffffffffu, s1, 1);
        s1 += __shfl_xor_sync(0xffffffffu, s1, 2);
        if (tig == 0) { reds[r0 * 2 + wn] = s0; reds[(r0 + 8) * 2 + wn] = s1; }
        __syncthreads();
        const float inv0 = 1.0f / (reds[r0 * 2] + reds[r0 * 2 + 1]);
        const float inv1 = 1.0f / (reds[(r0 + 8) * 2] + reds[(r0 + 8) * 2 + 1]);

#pragma unroll
        for (int nt = 0; nt < 16; nt++) {
            const int col = wn * 128 + nt * 8 + tig * 2;
            *(uint32_t*)(smc + PH_O + r0 * P_ROW_B + col * 2) =
                pack_h2(acc[nt][0] * inv0, acc[nt][1] * inv0);
            *(uint32_t*)(smc + PH_O + (r0 + 8) * P_ROW_B + col * 2) =
                pack_h2(acc[nt][2] * inv1, acc[nt][3] * inv1);
        }
    }
    __syncthreads();

    const int vrow = tid >> 5;
    const int vc16 = (tid & 31);
    __half* ob = o + qoff;

    uint4 rv0, rv1;
    auto ldgv = [&](int ci) {
        const int s0 = (ci & 15) * 16;
        const int hh = ci >> 4;
        rv0 = *(const uint4*)(Vb + (size_t)(s0 + vrow) * D_ + hh * 256 + vc16 * 8);
        rv1 = *(const uint4*)(Vb + (size_t)(s0 + vrow + 8) * D_ + hh * 256 + vc16 * 8);
    };
    auto stsv = [&](int b) {
        char* base = smc + VH_O + b * V_BUF;
        *(uint4*)(base + vrow * V_ROW_B + vc16 * 16) = rv0;
        *(uint4*)(base + (vrow + 8) * V_ROW_B + vc16 * 16) = rv1;
    };

    for (int h = 0; h < 2; h++) {
        float oacc[16][4];
#pragma unroll
        for (int nt = 0; nt < 16; nt++)
#pragma unroll
            for (int i = 0; i < 4; i++) oacc[nt][i] = 0.0f;

        ldgv(h * 16); stsv(0); ldgv(h * 16 + 1);
        __syncthreads();

        for (int j = 0; j < 16; j++) {
            const int cur = j & 1;
            if (j + 1 < 16) stsv(cur ^ 1);
            if (j + 2 < 16) ldgv(h * 16 + j + 2);

            uint32_t af[4];
            ldsm_x4(af, smb + PH_O + pa + (uint32_t)j * 32);
            const uint32_t vb_ = smb + VH_O + (uint32_t)cur * V_BUF + va;
#pragma unroll
            for (int p = 0; p < 8; p++) {
                uint32_t bf[4];
                ldsm_x4_t(bf, vb_ + (uint32_t)p * 32);
                mma_f16(oacc[2*p    ], af, &bf[0]);
                mma_f16(oacc[2*p + 1], af, &bf[2]);
            }
            __syncthreads();
        }

#pragma unroll
        for (int nt = 0; nt < 16; nt++) {
            const int col = h * 256 + wn * 128 + nt * 8 + tig * 2;
            const int r0  = wm * 16 + g;
            *(uint32_t*)(ob + (size_t)r0 * D_ + col) =
                pack_h2(oacc[nt][0], oacc[nt][1]);
            *(uint32_t*)(ob + (size_t)(r0 + 8) * D_ + col) =
                pack_h2(oacc[nt][2], oacc[nt][3]);
        }
    }
}

// ---------------------------------------------------------------------------
extern "C" void kernel_launch(void* const* d_in, const int* in_sizes, int n_in,
                              void* d_out, int out_size)
{
    (void)in_sizes; (void)n_in; (void)out_size;
    const float* queries = (const float*)d_in[0];
    const float* keys    = (const float*)d_in[1];
    const float* values  = (const float*)d_in[2];
    const float* Wq      = (const float*)d_in[3];
    const float* bq      = (const float*)d_in[4];
    const float* Wkv     = (const float*)d_in[5];
    const float* bkv     = (const float*)d_in[6];
    const float* Wo      = (const float*)d_in[7];
    const float* bo      = (const float*)d_in[8];
    float* out = (float*)d_out;

    __half *aq, *ak, *av, *qh, *ql, *kh, *kl, *vh, *oh, *whq, *whkv, *who;
    cudaGetSymbolAddress((void**)&aq,   g_aq);
    cudaGetSymbolAddress((void**)&ak,   g_ak);
    cudaGetSymbolAddress((void**)&av,   g_av);
    cudaGetSymbolAddress((void**)&qh,   g_qh);
    cudaGetSymbolAddress((void**)&ql,   g_ql);
    cudaGetSymbolAddress((void**)&kh,   g_kh);
    cudaGetSymbolAddress((void**)&kl,   g_kl);
    cudaGetSymbolAddress((void**)&vh,   g_vh);
    cudaGetSymbolAddress((void**)&oh,   g_oh);
    cudaGetSymbolAddress((void**)&whq,  g_whq);
    cudaGetSymbolAddress((void**)&whkv, g_whkv);
    cudaGetSymbolAddress((void**)&who,  g_who);

    (void)cudaFuncSetAttribute(attn_f16_kernel,
                               cudaFuncAttributeMaxDynamicSharedMemorySize,
                               ATTN_SMEM);
    (void)cudaFuncSetAttribute(gemm_qkv,
                               cudaFuncAttributeMaxDynamicSharedMemorySize,
                               GEMM_SMEM);
    (void)cudaFuncSetAttribute(gemm_o,
                               cudaFuncAttributeMaxDynamicSharedMemorySize,
                               GEMM_SMEM);

    // Converters
    convert_w3<<<384, 256>>>(Wq, whq, Wkv, whkv, Wo, who);
    convert_a3<<<24576, 256>>>(queries, aq, keys, ak, values, av);

    // Fused q/k/v projections (BK=64, all-cp.async)
    dim3 gqkv(D_ / 128, NQ / 128, 3);   // (4, 256, 3)
    gemm_qkv<<<gqkv, 256, GEMM_SMEM>>>(aq, ak, av, whq, whkv, bq, bkv,
                                       qh, ql, kh, kl, vh);

    // Attention
    attn_f16_kernel<<<B_ * L_ * (C_ / 64), 256, ATTN_SMEM>>>(qh, ql, kh, kl, vh, oh);

    // Output projection
    dim3 go(D_ / 128, NQ / 128);        // (4, 256)
    gemm_o<<<go, 256, GEMM_SMEM>>>(oh, who, bo, out);
}